// round 15
// baseline (speedup 1.0000x reference)
#include <cuda_runtime.h>
#include <cuda_fp16.h>
#include <cstdint>

// Problem constants
#define BB    64
#define CDIM  128
#define NPX   1024
#define WDIM  147584          // 128*128*9 + 128
#define WOFF  147456
#define NCHUNK 4
#define BCH   (BB / NCHUNK)   // 16 samples per pipeline chunk

// ---------------------------------------------------------------------------
// Device scratch
// w_h   : fp16 conv weights            [b][tap=9][o=128][c=128]
// g_padh: fp16 projected input         [b][y=34][x=32][c=128]  (y pads = 0)
// ---------------------------------------------------------------------------
__device__ __half w_h   [(size_t)BB * 9 * CDIM * CDIM];
__device__ __half g_padh[(size_t)BB * 34 * 32 * CDIM];

// ===========================================================================
// helpers
// ===========================================================================
__device__ __forceinline__ uint32_t smem_u32(const void* p) {
    uint32_t a;
    asm("{ .reg .u64 t; cvta.to.shared.u64 t, %1; cvt.u32.u64 %0, t; }"
        : "=r"(a) : "l"(p));
    return a;
}

#define CP_ASYNC16(dst_u32, src_ptr) \
    asm volatile("cp.async.cg.shared.global [%0], [%1], 16;" \
                 :: "r"(dst_u32), "l"(src_ptr) : "memory")
#define CP_COMMIT() asm volatile("cp.async.commit_group;" ::: "memory")
#define CP_WAIT(N)  asm volatile("cp.async.wait_group %0;" :: "n"(N) : "memory")

#define LDSM_X4(r0,r1,r2,r3,addr) \
    asm volatile("ldmatrix.sync.aligned.m8n8.x4.shared.b16 {%0,%1,%2,%3}, [%4];" \
                 : "=r"(r0),"=r"(r1),"=r"(r2),"=r"(r3) : "r"(addr))
#define LDSM_X4T(r0,r1,r2,r3,addr) \
    asm volatile("ldmatrix.sync.aligned.m8n8.x4.trans.shared.b16 {%0,%1,%2,%3}, [%4];" \
                 : "=r"(r0),"=r"(r1),"=r"(r2),"=r"(r3) : "r"(addr))

// m16n8k16 fp16 MMA, fp32 accumulate
__device__ __forceinline__ void mma_f16(float* d, const uint32_t* a,
                                        uint32_t b0, uint32_t b1) {
    asm volatile(
        "mma.sync.aligned.m16n8k16.row.col.f32.f16.f16.f32 "
        "{%0,%1,%2,%3}, {%4,%5,%6,%7}, {%8,%9}, {%0,%1,%2,%3};"
        : "+f"(d[0]), "+f"(d[1]), "+f"(d[2]), "+f"(d[3])
        : "r"(a[0]), "r"(a[1]), "r"(a[2]), "r"(a[3]), "r"(b0), "r"(b1));
}

__device__ __forceinline__ uint2 f4_to_h4(float4 v) {
    __half2 h0 = __floats2half2_rn(v.x, v.y);
    __half2 h1 = __floats2half2_rn(v.z, v.w);
    uint2 u;
    u.x = *reinterpret_cast<uint32_t*>(&h0);
    u.y = *reinterpret_cast<uint32_t*>(&h1);
    return u;
}

// ===========================================================================
// Kernel 0 (stream s2): wtrans -> w_h (conv-only dependency)
//   w_h[b][tap][o][c] = half(qrep[b, o*1152 + c*9 + tap])
// ===========================================================================
#define PREP_SMEM (16 * 1152 * 4)        // 73728 B

__global__ __launch_bounds__(256) void prep_w_kernel(const float* __restrict__ qrep)
{
    extern __shared__ float s[];
    const int blk = blockIdx.x, tid = threadIdx.x;
    const int b = blk >> 3, obase = (blk & 7) * 16;
    const float* src = qrep + (size_t)b * WDIM + obase * 1152;
    #pragma unroll
    for (int i = 0; i < 18; i++) {
        int idx = tid + i * 256;
        *reinterpret_cast<float4*>(s + idx * 4) =
            *reinterpret_cast<const float4*>(src + idx * 4);
    }
    __syncthreads();
    #pragma unroll
    for (int i = 0; i < 18; i++) {
        int idx = tid + i * 256;
        int tap = idx >> 9, rem = idx & 511;
        int o = rem >> 5, c4 = rem & 31;
        const float* row = s + o * 1152 + tap;
        __half2 h0 = __floats2half2_rn(row[(c4*4+0)*9], row[(c4*4+1)*9]);
        __half2 h1 = __floats2half2_rn(row[(c4*4+2)*9], row[(c4*4+3)*9]);
        uint2 u;
        u.x = *reinterpret_cast<uint32_t*>(&h0);
        u.y = *reinterpret_cast<uint32_t*>(&h1);
        *reinterpret_cast<uint2*>(
            w_h + (((size_t)b * 9 + tap) * CDIM + obase + o) * CDIM + c4*4) = u;
    }
}

// ===========================================================================
// Kernel 1: projection, fp16 m16n8k16, INPUT-DIRECT (R14-proven) + b0 offset.
// ===========================================================================
#define SH 72                                    // A smem row stride (halves)
#define PBSTH 136                                // B smem k-row stride (halves)
#define APH (128 * SH)                           // 9216 halves (A operand)
#define BPH (64 * PBSTH)                         // 8704 halves (B operand)
#define PSTGH (APH + BPH)                        // 17920 halves per stage
#define PROJ_SMEM (3 * PSTGH * 2)                // 107520 B
#define PNST 4

__global__ __launch_bounds__(256, 2) void proj_kernel(
    const float* __restrict__ lhs, const float* __restrict__ rhs,
    const float* __restrict__ pw,  const float* __restrict__ pb, int b0)
{
    extern __shared__ __half smh[];
    const int tid = threadIdx.x, lane = tid & 31, warp = tid >> 5;
    const int g = lane >> 2, q = lane & 3;
    const int ow = warp & 1, pwv = warp >> 1;
    const int b = blockIdx.y + b0, pxbase = blockIdx.x * 128;
    const uint32_t sbase = smem_u32(smh);

    auto fill = [&](int s) {
        __half* sa = smh + (s % 3) * PSTGH;
        __half* sb = sa + APH;
        #pragma unroll
        for (int i = 0; i < 8; i++) {            // A: pw [128 o][64 c]
            int f = tid + i * 256;
            int r = f >> 4, c4 = f & 15;
            float4 v = *reinterpret_cast<const float4*>(pw + r * 256 + s * 64 + c4 * 4);
            *reinterpret_cast<uint2*>(sa + r * SH + c4 * 4) = f4_to_h4(v);
        }
        #pragma unroll
        for (int i = 0; i < 8; i++) {            // B: cat [64 c][128 px]
            int f = tid + i * 256;
            int r = f >> 5, p4 = f & 31;
            int c = s * 64 + r;
            const float* src = (c < CDIM)
                ? (lhs + ((size_t)b * CDIM + c) * NPX + pxbase + p4 * 4)
                : (rhs + ((size_t)b * CDIM + (c - CDIM)) * NPX + pxbase + p4 * 4);
            float4 v = *reinterpret_cast<const float4*>(src);
            *reinterpret_cast<uint2*>(sb + r * PBSTH + p4 * 4) = f4_to_h4(v);
        }
    };

    const int aRow = ((lane >> 3) & 1) * 8 + (lane & 7);
    const int aK   = (lane >> 4) * 8;

    float acc[4][4][4];
    #pragma unroll
    for (int mt = 0; mt < 4; mt++)
        #pragma unroll
        for (int nt = 0; nt < 4; nt++)
            #pragma unroll
            for (int k = 0; k < 4; k++) acc[mt][nt][k] = 0.f;

    fill(0);
    for (int s = 0; s < PNST; s++) {
        __syncthreads();
        if (s + 1 < PNST) fill(s + 1);

        const uint32_t aBase = sbase + ((s % 3) * PSTGH) * 2;
        const uint32_t bBase = aBase + APH * 2;
        #pragma unroll
        for (int j = 0; j < 4; j++) {
            uint32_t af[4][4], bf[2][4];
            #pragma unroll
            for (int mt = 0; mt < 4; mt++) {
                uint32_t addr = aBase +
                    ((ow * 64 + mt * 16 + aRow) * SH + j * 16 + aK) * 2;
                LDSM_X4(af[mt][0], af[mt][1], af[mt][2], af[mt][3], addr);
            }
            #pragma unroll
            for (int ntp = 0; ntp < 2; ntp++) {
                uint32_t addr = bBase +
                    ((j * 16 + aRow) * PBSTH + pwv * 32 + ntp * 16 + aK) * 2;
                LDSM_X4T(bf[ntp][0], bf[ntp][1], bf[ntp][2], bf[ntp][3], addr);
            }
            #pragma unroll
            for (int nt = 0; nt < 4; nt++) {
                uint32_t b0r = bf[nt >> 1][(nt & 1) * 2];
                uint32_t b1r = bf[nt >> 1][(nt & 1) * 2 + 1];
                #pragma unroll
                for (int mt = 0; mt < 4; mt++)
                    mma_f16(acc[mt][nt], af[mt], b0r, b1r);
            }
        }
    }
    __syncthreads();                             // smem reused as T below

    float* T = reinterpret_cast<float*>(smh);    // [128 px][132]
    #pragma unroll
    for (int mt = 0; mt < 4; mt++) {
        int o = ow * 64 + mt * 16 + g;
        float bl = __ldg(pb + o), bh = __ldg(pb + o + 8);
        #pragma unroll
        for (int nt = 0; nt < 4; nt++) {
            int n0 = pwv * 32 + nt * 8 + 2 * q;
            T[n0 * 132 + o]           = acc[mt][nt][0] + bl;
            T[(n0 + 1) * 132 + o]     = acc[mt][nt][1] + bl;
            T[n0 * 132 + o + 8]       = acc[mt][nt][2] + bh;
            T[(n0 + 1) * 132 + o + 8] = acc[mt][nt][3] + bh;
        }
    }
    __syncthreads();
    #pragma unroll
    for (int i = 0; i < 16; i++) {
        int idx = tid + i * 256;
        int row = idx >> 5, c4 = idx & 31;
        int px = pxbase + row, y = px >> 5, x = px & 31;
        float4 v = *reinterpret_cast<const float4*>(T + row * 132 + c4 * 4);
        *reinterpret_cast<uint2*>(
            g_padh + (((size_t)b * 34 + 1 + y) * 32 + x) * CDIM + c4 * 4) = f4_to_h4(v);
    }
}

// ===========================================================================
// Kernel 2: conv, fp16 m16n8k16, RESIDENT B + streamed A (R10) + b0 offset.
// ===========================================================================
#define CBH 136                                  // B smem (row,x) stride (halves)
#define B_RES (6 * 34 * CBH)                     // 27744 halves
#define A_STG (128 * SH)                         // 9216 halves
#define CONV_SMEM ((B_RES + 3 * A_STG) * 2)      // 110784 B
#define NSTG 18

__global__ __launch_bounds__(256, 2) void conv_kernel(
    const float* __restrict__ qrep, float* __restrict__ out, int b0)
{
    extern __shared__ __half smh[];
    const int tid = threadIdx.x, lane = tid & 31, warp = tid >> 5;
    const int g = lane >> 2, q = lane & 3;
    const int ow = warp & 1, pwv = warp >> 1;
    const int ytile = blockIdx.x, b = blockIdx.y + b0;
    const uint32_t sbase = smem_u32(smh);

    #pragma unroll
    for (int i = tid; i < 6 * 2 * 16; i += 256) {
        int rr = i >> 5, rem = i & 31;
        int side = rem >> 4, u = rem & 15;
        int x = side ? 33 : 0;
        *reinterpret_cast<uint4*>(smh + (rr * 34 + x) * CBH + u * 8) =
            make_uint4(0, 0, 0, 0);
    }
    {
        const __half* bsrc = g_padh + ((size_t)b * 34 + ytile * 4) * 32 * CDIM;
        #pragma unroll
        for (int i = 0; i < 12; i++) {
            int f = tid + i * 256;
            int k16 = f & 15, x = (f >> 4) & 31, rr = f >> 9;
            CP_ASYNC16(sbase + ((rr * 34 + x + 1) * CBH + k16 * 8) * 2,
                       bsrc + (rr * 32 + x) * CDIM + k16 * 8);
        }
        CP_COMMIT();
    }

    const __half* wbase = w_h + (size_t)b * 9 * CDIM * CDIM;
    auto issueA = [&](int s) {
        const int tap = s >> 1, kc = s & 1;
        const uint32_t sa = sbase + (B_RES + (s % 3) * A_STG) * 2;
        const __half* wsrc = wbase + tap * (CDIM * CDIM) + kc * 64;
        #pragma unroll
        for (int i = 0; i < 4; i++) {
            int f = tid + i * 256;
            int r = f >> 3, k16 = f & 7;
            CP_ASYNC16(sa + (r * SH + k16 * 8) * 2, wsrc + r * CDIM + k16 * 8);
        }
        CP_COMMIT();
    };

    const int aRow = ((lane >> 3) & 1) * 8 + (lane & 7);
    const int aK   = (lane >> 4) * 8;
    const int m    = lane >> 3;
    const int bRow = (m >> 1) * 8 + (lane & 7);
    const int bK   = (m & 1) * 8;
    int rrB[2], xB[2];
    #pragma unroll
    for (int ntp = 0; ntp < 2; ntp++) {
        int px = pwv * 32 + ntp * 16 + bRow;
        rrB[ntp] = px >> 5;
        xB[ntp]  = px & 31;
    }

    float acc[4][4][4];
    #pragma unroll
    for (int mt = 0; mt < 4; mt++)
        #pragma unroll
        for (int nt = 0; nt < 4; nt++)
            #pragma unroll
            for (int k = 0; k < 4; k++) acc[mt][nt][k] = 0.f;

    issueA(0); issueA(1);

    for (int s = 0; s < NSTG; s++) {
        if (s + 1 < NSTG) CP_WAIT(1);
        else              CP_WAIT(0);
        __syncthreads();
        if (s + 2 < NSTG) issueA(s + 2);

        const int tap = s >> 1, kc = s & 1;
        const int dy = tap / 3, dx = tap % 3;
        const uint32_t aBase = sbase + (B_RES + (s % 3) * A_STG) * 2;

        #pragma unroll
        for (int j = 0; j < 4; j++) {
            uint32_t af[4][4], bf[2][4];
            #pragma unroll
            for (int mt = 0; mt < 4; mt++) {
                uint32_t addr = aBase +
                    ((ow * 64 + mt * 16 + aRow) * SH + j * 16 + aK) * 2;
                LDSM_X4(af[mt][0], af[mt][1], af[mt][2], af[mt][3], addr);
            }
            #pragma unroll
            for (int ntp = 0; ntp < 2; ntp++) {
                uint32_t addr = sbase +
                    (((rrB[ntp] + dy) * 34 + xB[ntp] + dx) * CBH +
                     kc * 64 + j * 16 + bK) * 2;
                LDSM_X4(bf[ntp][0], bf[ntp][1], bf[ntp][2], bf[ntp][3], addr);
            }
            #pragma unroll
            for (int nt = 0; nt < 4; nt++) {
                uint32_t b0r = bf[nt >> 1][(nt & 1) * 2];
                uint32_t b1r = bf[nt >> 1][(nt & 1) * 2 + 1];
                #pragma unroll
                for (int mt = 0; mt < 4; mt++)
                    mma_f16(acc[mt][nt], af[mt], b0r, b1r);
            }
        }
    }

    const float* bsrc = qrep + (size_t)b * WDIM + WOFF;
    #pragma unroll
    for (int mt = 0; mt < 4; mt++) {
        int o  = ow * 64 + mt * 16 + g;
        float bl = __ldg(bsrc + o), bh = __ldg(bsrc + o + 8);
        #pragma unroll
        for (int nt = 0; nt < 4; nt++) {
            int px = ytile * 128 + pwv * 32 + nt * 8 + 2 * q;
            float2 v0 = make_float2(acc[mt][nt][0] + bl, acc[mt][nt][1] + bl);
            float2 v1 = make_float2(acc[mt][nt][2] + bh, acc[mt][nt][3] + bh);
            *reinterpret_cast<float2*>(out + ((size_t)b * CDIM + o)     * NPX + px) = v0;
            *reinterpret_cast<float2*>(out + ((size_t)b * CDIM + o + 8) * NPX + px) = v1;
        }
    }
}

// ===========================================================================
extern "C" void kernel_launch(void* const* d_in, const int* in_sizes, int n_in,
                              void* d_out, int out_size)
{
    const float* qrep = (const float*)d_in[0];   // (64, 147584)
    const float* lhs  = (const float*)d_in[1];   // (64, 128, 32, 32)
    const float* rhs  = (const float*)d_in[2];   // (64, 128, 32, 32)
    const float* pw   = (const float*)d_in[3];   // (128, 256)
    const float* pb   = (const float*)d_in[4];   // (128,)
    float* out = (float*)d_out;                  // (64, 128, 32, 32)

    static cudaStream_t s2 = nullptr, s3 = nullptr;
    static cudaEvent_t evFork = nullptr, evW = nullptr, evEnd = nullptr;
    static cudaEvent_t evP[NCHUNK];
    static bool init_done = false;
    if (!init_done) {
        cudaFuncSetAttribute(prep_w_kernel,
            cudaFuncAttributeMaxDynamicSharedMemorySize, PREP_SMEM);
        cudaFuncSetAttribute(proj_kernel,
            cudaFuncAttributeMaxDynamicSharedMemorySize, PROJ_SMEM);
        cudaFuncSetAttribute(conv_kernel,
            cudaFuncAttributeMaxDynamicSharedMemorySize, CONV_SMEM);
        cudaStreamCreateWithFlags(&s2, cudaStreamNonBlocking);
        cudaStreamCreateWithFlags(&s3, cudaStreamNonBlocking);
        cudaEventCreateWithFlags(&evFork, cudaEventDisableTiming);
        cudaEventCreateWithFlags(&evW,    cudaEventDisableTiming);
        cudaEventCreateWithFlags(&evEnd,  cudaEventDisableTiming);
        for (int i = 0; i < NCHUNK; i++)
            cudaEventCreateWithFlags(&evP[i], cudaEventDisableTiming);
        init_done = true;
    }

    // Fork both side streams off the capture stream.
    cudaEventRecord(evFork, 0);
    cudaStreamWaitEvent(s2, evFork, 0);
    cudaStreamWaitEvent(s3, evFork, 0);

    // prep_w on s2; conv stream gates on it once.
    prep_w_kernel<<<512, 256, PREP_SMEM, s2>>>(qrep);
    cudaEventRecord(evW, s2);
    cudaStreamWaitEvent(s3, evW, 0);

    // Batch-pipelined chunks: proj(i) on default, conv(i) on s3 overlapping
    // proj(i+1..). Conv is tensor-bound, proj DRAM-bound -> complementary.
    for (int i = 0; i < NCHUNK; i++) {
        proj_kernel<<<dim3(8, BCH), 256, PROJ_SMEM>>>(lhs, rhs, pw, pb, i * BCH);
        cudaEventRecord(evP[i], 0);
        cudaStreamWaitEvent(s3, evP[i], 0);
        conv_kernel<<<dim3(8, BCH), 256, CONV_SMEM, s3>>>(qrep, out, i * BCH);
    }

    // Join s3 (and transitively s2) back into the capture stream.
    cudaEventRecord(evEnd, s3);
    cudaStreamWaitEvent(0, evEnd, 0);
}

// round 16
// speedup vs baseline: 1.0992x; 1.0992x over previous
#include <cuda_runtime.h>
#include <cuda_fp16.h>
#include <cstdint>

// Problem constants
#define BB    64
#define CDIM  128
#define NPX   1024
#define WDIM  147584          // 128*128*9 + 128
#define WOFF  147456

// ---------------------------------------------------------------------------
// Device scratch
// w_h   : fp16 conv weights            [b][tap=9][o=128][c=128]
// g_padh: fp16 projected input         [b][y=34][x=32][c=128]  (y pads = 0)
// ---------------------------------------------------------------------------
__device__ __half w_h   [(size_t)BB * 9 * CDIM * CDIM];
__device__ __half g_padh[(size_t)BB * 34 * 32 * CDIM];

// ===========================================================================
// helpers
// ===========================================================================
__device__ __forceinline__ uint32_t smem_u32(const void* p) {
    uint32_t a;
    asm("{ .reg .u64 t; cvta.to.shared.u64 t, %1; cvt.u32.u64 %0, t; }"
        : "=r"(a) : "l"(p));
    return a;
}

#define CP_ASYNC16(dst_u32, src_ptr) \
    asm volatile("cp.async.cg.shared.global [%0], [%1], 16;" \
                 :: "r"(dst_u32), "l"(src_ptr) : "memory")
#define CP_COMMIT() asm volatile("cp.async.commit_group;" ::: "memory")
#define CP_WAIT(N)  asm volatile("cp.async.wait_group %0;" :: "n"(N) : "memory")

#define LDSM_X4(r0,r1,r2,r3,addr) \
    asm volatile("ldmatrix.sync.aligned.m8n8.x4.shared.b16 {%0,%1,%2,%3}, [%4];" \
                 : "=r"(r0),"=r"(r1),"=r"(r2),"=r"(r3) : "r"(addr))
#define LDSM_X4T(r0,r1,r2,r3,addr) \
    asm volatile("ldmatrix.sync.aligned.m8n8.x4.trans.shared.b16 {%0,%1,%2,%3}, [%4];" \
                 : "=r"(r0),"=r"(r1),"=r"(r2),"=r"(r3) : "r"(addr))

// m16n8k16 fp16 MMA, fp32 accumulate
__device__ __forceinline__ void mma_f16(float* d, const uint32_t* a,
                                        uint32_t b0, uint32_t b1) {
    asm volatile(
        "mma.sync.aligned.m16n8k16.row.col.f32.f16.f16.f32 "
        "{%0,%1,%2,%3}, {%4,%5,%6,%7}, {%8,%9}, {%0,%1,%2,%3};"
        : "+f"(d[0]), "+f"(d[1]), "+f"(d[2]), "+f"(d[3])
        : "r"(a[0]), "r"(a[1]), "r"(a[2]), "r"(a[3]), "r"(b0), "r"(b1));
}

__device__ __forceinline__ uint2 f4_to_h4(float4 v) {
    __half2 h0 = __floats2half2_rn(v.x, v.y);
    __half2 h1 = __floats2half2_rn(v.z, v.w);
    uint2 u;
    u.x = *reinterpret_cast<uint32_t*>(&h0);
    u.y = *reinterpret_cast<uint32_t*>(&h1);
    return u;
}

// ===========================================================================
// Kernel 0 (stream s2): wtrans -> w_h (conv-only dependency)
//   w_h[b][tap][o][c] = half(qrep[b, o*1152 + c*9 + tap])
// ===========================================================================
#define PREP_SMEM (16 * 1152 * 4)        // 73728 B

__global__ __launch_bounds__(256) void prep_w_kernel(const float* __restrict__ qrep)
{
    extern __shared__ float s[];
    const int blk = blockIdx.x, tid = threadIdx.x;
    const int b = blk >> 3, obase = (blk & 7) * 16;
    const float* src = qrep + (size_t)b * WDIM + obase * 1152;
    #pragma unroll
    for (int i = 0; i < 18; i++) {
        int idx = tid + i * 256;
        *reinterpret_cast<float4*>(s + idx * 4) =
            *reinterpret_cast<const float4*>(src + idx * 4);
    }
    __syncthreads();
    #pragma unroll
    for (int i = 0; i < 18; i++) {
        int idx = tid + i * 256;
        int tap = idx >> 9, rem = idx & 511;
        int o = rem >> 5, c4 = rem & 31;
        const float* row = s + o * 1152 + tap;
        __half2 h0 = __floats2half2_rn(row[(c4*4+0)*9], row[(c4*4+1)*9]);
        __half2 h1 = __floats2half2_rn(row[(c4*4+2)*9], row[(c4*4+3)*9]);
        uint2 u;
        u.x = *reinterpret_cast<uint32_t*>(&h0);
        u.y = *reinterpret_cast<uint32_t*>(&h1);
        *reinterpret_cast<uint2*>(
            w_h + (((size_t)b * 9 + tap) * CDIM + obase + o) * CDIM + c4*4) = u;
    }
}

// ===========================================================================
// Kernel 1: projection, fp16 m16n8k16, INPUT-DIRECT with register-staged
// B pipeline: loadB(s+2)->regs, storeB(s+1) regs->smem, compute(s).
// A = [o][c] stride 72 (non-trans LDSM); B = [k][px] stride 136 (trans LDSM).
// CTA: 128 o x 128 px, 8 warps (2o x 4px). K=256: 4 stages, 3-ring, 1 sync.
// ===========================================================================
#define SH 72                                    // A smem row stride (halves)
#define PBSTH 136                                // B smem k-row stride (halves)
#define APH (128 * SH)                           // 9216 halves (A operand)
#define BPH (64 * PBSTH)                         // 8704 halves (B operand)
#define PSTGH (APH + BPH)                        // 17920 halves per stage
#define PROJ_SMEM (3 * PSTGH * 2)                // 107520 B
#define PNST 4

__global__ __launch_bounds__(256, 2) void proj_kernel(
    const float* __restrict__ lhs, const float* __restrict__ rhs,
    const float* __restrict__ pw,  const float* __restrict__ pb)
{
    extern __shared__ __half smh[];
    const int tid = threadIdx.x, lane = tid & 31, warp = tid >> 5;
    const int g = lane >> 2, q = lane & 3;
    const int ow = warp & 1, pwv = warp >> 1;
    const int b = blockIdx.y, pxbase = blockIdx.x * 128;
    const uint32_t sbase = smem_u32(smh);

    // A fill: pw [128 o][64 c] fp32 -> fp16, stride 72 (pw is L2-resident)
    auto fillA = [&](int s) {
        __half* sa = smh + (s % 3) * PSTGH;
        #pragma unroll
        for (int i = 0; i < 8; i++) {
            int f = tid + i * 256;
            int r = f >> 4, c4 = f & 15;
            float4 v = *reinterpret_cast<const float4*>(pw + r * 256 + s * 64 + c4 * 4);
            *reinterpret_cast<uint2*>(sa + r * SH + c4 * 4) = f4_to_h4(v);
        }
    };
    // B load: issue 8 float4 LDGs for stage s into registers (no conversion
    // yet -- conversion would force an immediate wait on the loads).
    auto loadB = [&](int s, float4* vr) {
        #pragma unroll
        for (int i = 0; i < 8; i++) {
            int f = tid + i * 256;
            int r = f >> 5, p4 = f & 31;
            int c = s * 64 + r;
            const float* src = (c < CDIM)
                ? (lhs + ((size_t)b * CDIM + c) * NPX + pxbase + p4 * 4)
                : (rhs + ((size_t)b * CDIM + (c - CDIM)) * NPX + pxbase + p4 * 4);
            vr[i] = *reinterpret_cast<const float4*>(src);
        }
    };
    // B store: convert staged registers and write stage s smem tile.
    auto storeB = [&](int s, const float4* vr) {
        __half* sb = smh + (s % 3) * PSTGH + APH;
        #pragma unroll
        for (int i = 0; i < 8; i++) {
            int f = tid + i * 256;
            int r = f >> 5, p4 = f & 31;
            *reinterpret_cast<uint2*>(sb + r * PBSTH + p4 * 4) = f4_to_h4(vr[i]);
        }
    };

    const int aRow = ((lane >> 3) & 1) * 8 + (lane & 7);
    const int aK   = (lane >> 4) * 8;

    float acc[4][4][4];
    #pragma unroll
    for (int mt = 0; mt < 4; mt++)
        #pragma unroll
        for (int nt = 0; nt < 4; nt++)
            #pragma unroll
            for (int k = 0; k < 4; k++) acc[mt][nt][k] = 0.f;

    float4 vr[8];
    // Prologue: stage 0 fully in smem; stage 1 A in smem, B staged in regs.
    fillA(0);
    loadB(0, vr); storeB(0, vr);
    loadB(1, vr);
    fillA(1);

    for (int s = 0; s < PNST; s++) {
        __syncthreads();                          // buf s fully visible
        if (s + 1 < PNST) storeB(s + 1, vr);      // slot (s+1)%3 = (s-2)%3, free
        if (s + 2 < PNST) { loadB(s + 2, vr); fillA(s + 2); }

        const uint32_t aBase = sbase + ((s % 3) * PSTGH) * 2;
        const uint32_t bBase = aBase + APH * 2;
        #pragma unroll
        for (int j = 0; j < 4; j++) {
            uint32_t af[4][4], bf[2][4];
            #pragma unroll
            for (int mt = 0; mt < 4; mt++) {
                uint32_t addr = aBase +
                    ((ow * 64 + mt * 16 + aRow) * SH + j * 16 + aK) * 2;
                LDSM_X4(af[mt][0], af[mt][1], af[mt][2], af[mt][3], addr);
            }
            #pragma unroll
            for (int ntp = 0; ntp < 2; ntp++) {
                uint32_t addr = bBase +
                    ((j * 16 + aRow) * PBSTH + pwv * 32 + ntp * 16 + aK) * 2;
                LDSM_X4T(bf[ntp][0], bf[ntp][1], bf[ntp][2], bf[ntp][3], addr);
            }
            #pragma unroll
            for (int nt = 0; nt < 4; nt++) {
                uint32_t b0r = bf[nt >> 1][(nt & 1) * 2];
                uint32_t b1r = bf[nt >> 1][(nt & 1) * 2 + 1];
                #pragma unroll
                for (int mt = 0; mt < 4; mt++)
                    mma_f16(acc[mt][nt], af[mt], b0r, b1r);
            }
        }
    }
    __syncthreads();                             // smem reused as T below

    // Epilogue: +bias, transpose through smem, fp16 store to g_padh
    float* T = reinterpret_cast<float*>(smh);    // [128 px][132]
    #pragma unroll
    for (int mt = 0; mt < 4; mt++) {
        int o = ow * 64 + mt * 16 + g;
        float bl = __ldg(pb + o), bh = __ldg(pb + o + 8);
        #pragma unroll
        for (int nt = 0; nt < 4; nt++) {
            int n0 = pwv * 32 + nt * 8 + 2 * q;
            T[n0 * 132 + o]           = acc[mt][nt][0] + bl;
            T[(n0 + 1) * 132 + o]     = acc[mt][nt][1] + bl;
            T[n0 * 132 + o + 8]       = acc[mt][nt][2] + bh;
            T[(n0 + 1) * 132 + o + 8] = acc[mt][nt][3] + bh;
        }
    }
    __syncthreads();
    #pragma unroll
    for (int i = 0; i < 16; i++) {
        int idx = tid + i * 256;
        int row = idx >> 5, c4 = idx & 31;
        int px = pxbase + row, y = px >> 5, x = px & 31;
        float4 v = *reinterpret_cast<const float4*>(T + row * 132 + c4 * 4);
        *reinterpret_cast<uint2*>(
            g_padh + (((size_t)b * 34 + 1 + y) * 32 + x) * CDIM + c4 * 4) = f4_to_h4(v);
    }
}

// ===========================================================================
// Kernel 2: conv, fp16 m16n8k16, RESIDENT B window + streamed A. (R10 proven)
// ===========================================================================
#define CBH 136                                  // B smem (row,x) stride (halves)
#define B_RES (6 * 34 * CBH)                     // 27744 halves
#define A_STG (128 * SH)                         // 9216 halves
#define CONV_SMEM ((B_RES + 3 * A_STG) * 2)      // 110784 B
#define NSTG 18

__global__ __launch_bounds__(256, 2) void conv_kernel(
    const float* __restrict__ qrep, float* __restrict__ out)
{
    extern __shared__ __half smh[];
    const int tid = threadIdx.x, lane = tid & 31, warp = tid >> 5;
    const int g = lane >> 2, q = lane & 3;
    const int ow = warp & 1, pwv = warp >> 1;
    const int ytile = blockIdx.x, b = blockIdx.y;
    const uint32_t sbase = smem_u32(smh);

    #pragma unroll
    for (int i = tid; i < 6 * 2 * 16; i += 256) {
        int rr = i >> 5, rem = i & 31;
        int side = rem >> 4, u = rem & 15;
        int x = side ? 33 : 0;
        *reinterpret_cast<uint4*>(smh + (rr * 34 + x) * CBH + u * 8) =
            make_uint4(0, 0, 0, 0);
    }
    {
        const __half* bsrc = g_padh + ((size_t)b * 34 + ytile * 4) * 32 * CDIM;
        #pragma unroll
        for (int i = 0; i < 12; i++) {
            int f = tid + i * 256;
            int k16 = f & 15, x = (f >> 4) & 31, rr = f >> 9;
            CP_ASYNC16(sbase + ((rr * 34 + x + 1) * CBH + k16 * 8) * 2,
                       bsrc + (rr * 32 + x) * CDIM + k16 * 8);
        }
        CP_COMMIT();
    }

    const __half* wbase = w_h + (size_t)b * 9 * CDIM * CDIM;
    auto issueA = [&](int s) {
        const int tap = s >> 1, kc = s & 1;
        const uint32_t sa = sbase + (B_RES + (s % 3) * A_STG) * 2;
        const __half* wsrc = wbase + tap * (CDIM * CDIM) + kc * 64;
        #pragma unroll
        for (int i = 0; i < 4; i++) {
            int f = tid + i * 256;
            int r = f >> 3, k16 = f & 7;
            CP_ASYNC16(sa + (r * SH + k16 * 8) * 2, wsrc + r * CDIM + k16 * 8);
        }
        CP_COMMIT();
    };

    const int aRow = ((lane >> 3) & 1) * 8 + (lane & 7);
    const int aK   = (lane >> 4) * 8;
    const int m    = lane >> 3;
    const int bRow = (m >> 1) * 8 + (lane & 7);
    const int bK   = (m & 1) * 8;
    int rrB[2], xB[2];
    #pragma unroll
    for (int ntp = 0; ntp < 2; ntp++) {
        int px = pwv * 32 + ntp * 16 + bRow;
        rrB[ntp] = px >> 5;
        xB[ntp]  = px & 31;
    }

    float acc[4][4][4];
    #pragma unroll
    for (int mt = 0; mt < 4; mt++)
        #pragma unroll
        for (int nt = 0; nt < 4; nt++)
            #pragma unroll
            for (int k = 0; k < 4; k++) acc[mt][nt][k] = 0.f;

    issueA(0); issueA(1);

    for (int s = 0; s < NSTG; s++) {
        if (s + 1 < NSTG) CP_WAIT(1);
        else              CP_WAIT(0);
        __syncthreads();
        if (s + 2 < NSTG) issueA(s + 2);

        const int tap = s >> 1, kc = s & 1;
        const int dy = tap / 3, dx = tap % 3;
        const uint32_t aBase = sbase + (B_RES + (s % 3) * A_STG) * 2;

        #pragma unroll
        for (int j = 0; j < 4; j++) {
            uint32_t af[4][4], bf[2][4];
            #pragma unroll
            for (int mt = 0; mt < 4; mt++) {
                uint32_t addr = aBase +
                    ((ow * 64 + mt * 16 + aRow) * SH + j * 16 + aK) * 2;
                LDSM_X4(af[mt][0], af[mt][1], af[mt][2], af[mt][3], addr);
            }
            #pragma unroll
            for (int ntp = 0; ntp < 2; ntp++) {
                uint32_t addr = sbase +
                    (((rrB[ntp] + dy) * 34 + xB[ntp] + dx) * CBH +
                     kc * 64 + j * 16 + bK) * 2;
                LDSM_X4(bf[ntp][0], bf[ntp][1], bf[ntp][2], bf[ntp][3], addr);
            }
            #pragma unroll
            for (int nt = 0; nt < 4; nt++) {
                uint32_t b0r = bf[nt >> 1][(nt & 1) * 2];
                uint32_t b1r = bf[nt >> 1][(nt & 1) * 2 + 1];
                #pragma unroll
                for (int mt = 0; mt < 4; mt++)
                    mma_f16(acc[mt][nt], af[mt], b0r, b1r);
            }
        }
    }

    const float* bsrc = qrep + (size_t)b * WDIM + WOFF;
    #pragma unroll
    for (int mt = 0; mt < 4; mt++) {
        int o  = ow * 64 + mt * 16 + g;
        float bl = __ldg(bsrc + o), bh = __ldg(bsrc + o + 8);
        #pragma unroll
        for (int nt = 0; nt < 4; nt++) {
            int px = ytile * 128 + pwv * 32 + nt * 8 + 2 * q;
            float2 v0 = make_float2(acc[mt][nt][0] + bl, acc[mt][nt][1] + bl);
            float2 v1 = make_float2(acc[mt][nt][2] + bh, acc[mt][nt][3] + bh);
            *reinterpret_cast<float2*>(out + ((size_t)b * CDIM + o)     * NPX + px) = v0;
            *reinterpret_cast<float2*>(out + ((size_t)b * CDIM + o + 8) * NPX + px) = v1;
        }
    }
}

// ===========================================================================
extern "C" void kernel_launch(void* const* d_in, const int* in_sizes, int n_in,
                              void* d_out, int out_size)
{
    const float* qrep = (const float*)d_in[0];   // (64, 147584)
    const float* lhs  = (const float*)d_in[1];   // (64, 128, 32, 32)
    const float* rhs  = (const float*)d_in[2];   // (64, 128, 32, 32)
    const float* pw   = (const float*)d_in[3];   // (128, 256)
    const float* pb   = (const float*)d_in[4];   // (128,)
    float* out = (float*)d_out;                  // (64, 128, 32, 32)

    static cudaStream_t s2 = nullptr;
    static cudaEvent_t evFork = nullptr, evJoin = nullptr;
    static bool init_done = false;
    if (!init_done) {
        cudaFuncSetAttribute(prep_w_kernel,
            cudaFuncAttributeMaxDynamicSharedMemorySize, PREP_SMEM);
        cudaFuncSetAttribute(proj_kernel,
            cudaFuncAttributeMaxDynamicSharedMemorySize, PROJ_SMEM);
        cudaFuncSetAttribute(conv_kernel,
            cudaFuncAttributeMaxDynamicSharedMemorySize, CONV_SMEM);
        cudaStreamCreateWithFlags(&s2, cudaStreamNonBlocking);
        cudaEventCreateWithFlags(&evFork, cudaEventDisableTiming);
        cudaEventCreateWithFlags(&evJoin, cudaEventDisableTiming);
        init_done = true;
    }

    // Fork: wtrans (conv-only dependency) on s2, fully parallel with proj.
    cudaEventRecord(evFork, 0);
    cudaStreamWaitEvent(s2, evFork, 0);
    prep_w_kernel<<<512, 256, PREP_SMEM, s2>>>(qrep);

    proj_kernel<<<dim3(8, BB), 256, PROJ_SMEM>>>(lhs, rhs, pw, pb);

    // Join: conv needs w_h (s2) and g_padh (default stream).
    cudaEventRecord(evJoin, s2);
    cudaStreamWaitEvent(0, evJoin, 0);
    conv_kernel<<<dim3(8, BB), 256, CONV_SMEM>>>(qrep, out);
}

// round 17
// speedup vs baseline: 1.1923x; 1.0847x over previous
#include <cuda_runtime.h>
#include <cuda_fp16.h>
#include <cstdint>

// Problem constants
#define BB    64
#define CDIM  128
#define NPX   1024
#define WDIM  147584          // 128*128*9 + 128
#define WOFF  147456

// ---------------------------------------------------------------------------
// Device scratch + dependency flags (.bss zero at first run; tail kernel
// re-zeroes flags each launch so graph replays are deterministic)
// ---------------------------------------------------------------------------
__device__ __half w_h   [(size_t)BB * 9 * CDIM * CDIM];
__device__ __half g_padh[(size_t)BB * 34 * 32 * CDIM];
__device__ int    g_flagW[BB];        // prep_w blocks done per sample (8 each)
__device__ int    g_flagP[BB * 8];    // proj tile (b, pxtile) done

// ===========================================================================
// helpers
// ===========================================================================
__device__ __forceinline__ uint32_t smem_u32(const void* p) {
    uint32_t a;
    asm("{ .reg .u64 t; cvta.to.shared.u64 t, %1; cvt.u32.u64 %0, t; }"
        : "=r"(a) : "l"(p));
    return a;
}

#define CP_ASYNC16(dst_u32, src_ptr) \
    asm volatile("cp.async.cg.shared.global [%0], [%1], 16;" \
                 :: "r"(dst_u32), "l"(src_ptr) : "memory")
#define CP_COMMIT() asm volatile("cp.async.commit_group;" ::: "memory")
#define CP_WAIT(N)  asm volatile("cp.async.wait_group %0;" :: "n"(N) : "memory")

#define LDSM_X4(r0,r1,r2,r3,addr) \
    asm volatile("ldmatrix.sync.aligned.m8n8.x4.shared.b16 {%0,%1,%2,%3}, [%4];" \
                 : "=r"(r0),"=r"(r1),"=r"(r2),"=r"(r3) : "r"(addr))
#define LDSM_X4T(r0,r1,r2,r3,addr) \
    asm volatile("ldmatrix.sync.aligned.m8n8.x4.trans.shared.b16 {%0,%1,%2,%3}, [%4];" \
                 : "=r"(r0),"=r"(r1),"=r"(r2),"=r"(r3) : "r"(addr))

__device__ __forceinline__ void mma_f16(float* d, const uint32_t* a,
                                        uint32_t b0, uint32_t b1) {
    asm volatile(
        "mma.sync.aligned.m16n8k16.row.col.f32.f16.f16.f32 "
        "{%0,%1,%2,%3}, {%4,%5,%6,%7}, {%8,%9}, {%0,%1,%2,%3};"
        : "+f"(d[0]), "+f"(d[1]), "+f"(d[2]), "+f"(d[3])
        : "r"(a[0]), "r"(a[1]), "r"(a[2]), "r"(a[3]), "r"(b0), "r"(b1));
}

__device__ __forceinline__ uint2 f4_to_h4(float4 v) {
    __half2 h0 = __floats2half2_rn(v.x, v.y);
    __half2 h1 = __floats2half2_rn(v.z, v.w);
    uint2 u;
    u.x = *reinterpret_cast<uint32_t*>(&h0);
    u.y = *reinterpret_cast<uint32_t*>(&h1);
    return u;
}

// Layout constants (R14-proven)
#define SH 72
#define PBSTH 136
#define APH (128 * SH)
#define BPH (64 * PBSTH)
#define PSTGH (APH + BPH)
#define PNST 4
#define CBH 136
#define B_RES (6 * 34 * CBH)
#define A_STG (128 * SH)
#define NSTG 18
#define FUSED_SMEM ((B_RES + 3 * A_STG) * 2)     // 110784 B (max of roles)

// ===========================================================================
// Fused kernel: role by blockIdx.x.
//  [0,512)    prep_w: w_h[b][tap][o][c]; release g_flagW[b]
//  [512,1024) proj:   g_padh tile (b,pxtile); release g_flagP[b*8+pxtile]
//  [1024,1536) conv:  acquire flagW[b]==8 and flagP[b][t-1..t+1], compute out
// Dependencies point strictly backward in blockIdx -> no deadlock under
// (near-)ordered CTA issuance.
// ===========================================================================
__global__ __launch_bounds__(256, 2) void fused_kernel(
    const float* __restrict__ qrep, const float* __restrict__ lhs,
    const float* __restrict__ rhs,  const float* __restrict__ pw,
    const float* __restrict__ pb,   float* __restrict__ out)
{
    extern __shared__ __half smh[];
    const int blk = blockIdx.x, tid = threadIdx.x;

    if (blk < 512) {
        // ================= prep_w role =================
        float* s = reinterpret_cast<float*>(smh);
        const int b = blk >> 3, obase = (blk & 7) * 16;
        const float* src = qrep + (size_t)b * WDIM + obase * 1152;
        #pragma unroll
        for (int i = 0; i < 18; i++) {
            int idx = tid + i * 256;
            *reinterpret_cast<float4*>(s + idx * 4) =
                *reinterpret_cast<const float4*>(src + idx * 4);
        }
        __syncthreads();
        #pragma unroll
        for (int i = 0; i < 18; i++) {
            int idx = tid + i * 256;
            int tap = idx >> 9, rem = idx & 511;
            int o = rem >> 5, c4 = rem & 31;
            const float* row = s + o * 1152 + tap;
            __half2 h0 = __floats2half2_rn(row[(c4*4+0)*9], row[(c4*4+1)*9]);
            __half2 h1 = __floats2half2_rn(row[(c4*4+2)*9], row[(c4*4+3)*9]);
            uint2 u;
            u.x = *reinterpret_cast<uint32_t*>(&h0);
            u.y = *reinterpret_cast<uint32_t*>(&h1);
            *reinterpret_cast<uint2*>(
                w_h + (((size_t)b * 9 + tap) * CDIM + obase + o) * CDIM + c4*4) = u;
        }
        __syncthreads();
        if (tid == 0) { __threadfence(); atomicAdd(&g_flagW[b], 1); }

    } else if (blk < 1024) {
        // ================= proj role (R14 input-direct) =================
        const int pblk = blk - 512;
        const int b = pblk >> 3, pxbase = (pblk & 7) * 128;
        const int lane = tid & 31, warp = tid >> 5;
        const int g = lane >> 2, q = lane & 3;
        const int ow = warp & 1, pwv = warp >> 1;
        const uint32_t sbase = smem_u32(smh);

        auto fill = [&](int s) {
            __half* sa = smh + (s % 3) * PSTGH;
            __half* sb = sa + APH;
            #pragma unroll
            for (int i = 0; i < 8; i++) {        // A: pw [128 o][64 c]
                int f = tid + i * 256;
                int r = f >> 4, c4 = f & 15;
                float4 v = *reinterpret_cast<const float4*>(
                    pw + r * 256 + s * 64 + c4 * 4);
                *reinterpret_cast<uint2*>(sa + r * SH + c4 * 4) = f4_to_h4(v);
            }
            #pragma unroll
            for (int i = 0; i < 8; i++) {        // B: cat [64 c][128 px]
                int f = tid + i * 256;
                int r = f >> 5, p4 = f & 31;
                int c = s * 64 + r;
                const float* src = (c < CDIM)
                    ? (lhs + ((size_t)b * CDIM + c) * NPX + pxbase + p4 * 4)
                    : (rhs + ((size_t)b * CDIM + (c - CDIM)) * NPX + pxbase + p4 * 4);
                float4 v = *reinterpret_cast<const float4*>(src);
                *reinterpret_cast<uint2*>(sb + r * PBSTH + p4 * 4) = f4_to_h4(v);
            }
        };

        const int aRow = ((lane >> 3) & 1) * 8 + (lane & 7);
        const int aK   = (lane >> 4) * 8;

        float acc[4][4][4];
        #pragma unroll
        for (int mt = 0; mt < 4; mt++)
            #pragma unroll
            for (int nt = 0; nt < 4; nt++)
                #pragma unroll
                for (int k = 0; k < 4; k++) acc[mt][nt][k] = 0.f;

        fill(0);
        for (int s = 0; s < PNST; s++) {
            __syncthreads();
            if (s + 1 < PNST) fill(s + 1);

            const uint32_t aBase = sbase + ((s % 3) * PSTGH) * 2;
            const uint32_t bBase = aBase + APH * 2;
            #pragma unroll
            for (int j = 0; j < 4; j++) {
                uint32_t af[4][4], bf[2][4];
                #pragma unroll
                for (int mt = 0; mt < 4; mt++) {
                    uint32_t addr = aBase +
                        ((ow * 64 + mt * 16 + aRow) * SH + j * 16 + aK) * 2;
                    LDSM_X4(af[mt][0], af[mt][1], af[mt][2], af[mt][3], addr);
                }
                #pragma unroll
                for (int ntp = 0; ntp < 2; ntp++) {
                    uint32_t addr = bBase +
                        ((j * 16 + aRow) * PBSTH + pwv * 32 + ntp * 16 + aK) * 2;
                    LDSM_X4T(bf[ntp][0], bf[ntp][1], bf[ntp][2], bf[ntp][3], addr);
                }
                #pragma unroll
                for (int nt = 0; nt < 4; nt++) {
                    uint32_t b0r = bf[nt >> 1][(nt & 1) * 2];
                    uint32_t b1r = bf[nt >> 1][(nt & 1) * 2 + 1];
                    #pragma unroll
                    for (int mt = 0; mt < 4; mt++)
                        mma_f16(acc[mt][nt], af[mt], b0r, b1r);
                }
            }
        }
        __syncthreads();

        float* T = reinterpret_cast<float*>(smh);    // [128 px][132]
        #pragma unroll
        for (int mt = 0; mt < 4; mt++) {
            int o = ow * 64 + mt * 16 + g;
            float bl = __ldg(pb + o), bh = __ldg(pb + o + 8);
            #pragma unroll
            for (int nt = 0; nt < 4; nt++) {
                int n0 = pwv * 32 + nt * 8 + 2 * q;
                T[n0 * 132 + o]           = acc[mt][nt][0] + bl;
                T[(n0 + 1) * 132 + o]     = acc[mt][nt][1] + bl;
                T[n0 * 132 + o + 8]       = acc[mt][nt][2] + bh;
                T[(n0 + 1) * 132 + o + 8] = acc[mt][nt][3] + bh;
            }
        }
        __syncthreads();
        #pragma unroll
        for (int i = 0; i < 16; i++) {
            int idx = tid + i * 256;
            int row = idx >> 5, c4 = idx & 31;
            int px = pxbase + row, y = px >> 5, x = px & 31;
            float4 v = *reinterpret_cast<const float4*>(T + row * 132 + c4 * 4);
            *reinterpret_cast<uint2*>(
                g_padh + (((size_t)b * 34 + 1 + y) * 32 + x) * CDIM + c4 * 4)
                = f4_to_h4(v);
        }
        __syncthreads();
        if (tid == 0) { __threadfence(); atomicAdd(&g_flagP[pblk], 1); }

    } else {
        // ================= conv role (R10/R14 resident-B) =================
        const int cblk = blk - 1024;
        const int b = cblk >> 3, ytile = cblk & 7;
        const int lane = tid & 31, warp = tid >> 5;
        const int g = lane >> 2, q = lane & 3;
        const int ow = warp & 1, pwv = warp >> 1;
        const uint32_t sbase = smem_u32(smh);

        // Acquire dependencies: all prep_w of sample b; proj tiles t-1..t+1.
        if (tid == 0) {
            while (atomicAdd(&g_flagW[b], 0) < 8) {}
            int p0 = (ytile > 0) ? ytile - 1 : 0;
            int p1 = (ytile < 7) ? ytile + 1 : 7;
            for (int p = p0; p <= p1; p++)
                while (atomicAdd(&g_flagP[b * 8 + p], 0) == 0) {}
        }
        __syncthreads();

        #pragma unroll
        for (int i = tid; i < 6 * 2 * 16; i += 256) {
            int rr = i >> 5, rem = i & 31;
            int side = rem >> 4, u = rem & 15;
            int x = side ? 33 : 0;
            *reinterpret_cast<uint4*>(smh + (rr * 34 + x) * CBH + u * 8) =
                make_uint4(0, 0, 0, 0);
        }
        {
            const __half* bsrc = g_padh + ((size_t)b * 34 + ytile * 4) * 32 * CDIM;
            #pragma unroll
            for (int i = 0; i < 12; i++) {
                int f = tid + i * 256;
                int k16 = f & 15, x = (f >> 4) & 31, rr = f >> 9;
                CP_ASYNC16(sbase + ((rr * 34 + x + 1) * CBH + k16 * 8) * 2,
                           bsrc + (rr * 32 + x) * CDIM + k16 * 8);
            }
            CP_COMMIT();
        }

        const __half* wbase = w_h + (size_t)b * 9 * CDIM * CDIM;
        auto issueA = [&](int s) {
            const int tap = s >> 1, kc = s & 1;
            const uint32_t sa = sbase + (B_RES + (s % 3) * A_STG) * 2;
            const __half* wsrc = wbase + tap * (CDIM * CDIM) + kc * 64;
            #pragma unroll
            for (int i = 0; i < 4; i++) {
                int f = tid + i * 256;
                int r = f >> 3, k16 = f & 7;
                CP_ASYNC16(sa + (r * SH + k16 * 8) * 2, wsrc + r * CDIM + k16 * 8);
            }
            CP_COMMIT();
        };

        const int aRow = ((lane >> 3) & 1) * 8 + (lane & 7);
        const int aK   = (lane >> 4) * 8;
        const int m    = lane >> 3;
        const int bRow = (m >> 1) * 8 + (lane & 7);
        const int bK   = (m & 1) * 8;
        int rrB[2], xB[2];
        #pragma unroll
        for (int ntp = 0; ntp < 2; ntp++) {
            int px = pwv * 32 + ntp * 16 + bRow;
            rrB[ntp] = px >> 5;
            xB[ntp]  = px & 31;
        }

        float acc[4][4][4];
        #pragma unroll
        for (int mt = 0; mt < 4; mt++)
            #pragma unroll
            for (int nt = 0; nt < 4; nt++)
                #pragma unroll
                for (int k = 0; k < 4; k++) acc[mt][nt][k] = 0.f;

        issueA(0); issueA(1);

        for (int s = 0; s < NSTG; s++) {
            if (s + 1 < NSTG) CP_WAIT(1);
            else              CP_WAIT(0);
            __syncthreads();
            if (s + 2 < NSTG) issueA(s + 2);

            const int tap = s >> 1, kc = s & 1;
            const int dy = tap / 3, dx = tap % 3;
            const uint32_t aBase = sbase + (B_RES + (s % 3) * A_STG) * 2;

            #pragma unroll
            for (int j = 0; j < 4; j++) {
                uint32_t af[4][4], bf[2][4];
                #pragma unroll
                for (int mt = 0; mt < 4; mt++) {
                    uint32_t addr = aBase +
                        ((ow * 64 + mt * 16 + aRow) * SH + j * 16 + aK) * 2;
                    LDSM_X4(af[mt][0], af[mt][1], af[mt][2], af[mt][3], addr);
                }
                #pragma unroll
                for (int ntp = 0; ntp < 2; ntp++) {
                    uint32_t addr = sbase +
                        (((rrB[ntp] + dy) * 34 + xB[ntp] + dx) * CBH +
                         kc * 64 + j * 16 + bK) * 2;
                    LDSM_X4(bf[ntp][0], bf[ntp][1], bf[ntp][2], bf[ntp][3], addr);
                }
                #pragma unroll
                for (int nt = 0; nt < 4; nt++) {
                    uint32_t b0r = bf[nt >> 1][(nt & 1) * 2];
                    uint32_t b1r = bf[nt >> 1][(nt & 1) * 2 + 1];
                    #pragma unroll
                    for (int mt = 0; mt < 4; mt++)
                        mma_f16(acc[mt][nt], af[mt], b0r, b1r);
                }
            }
        }

        const float* bsrc = qrep + (size_t)b * WDIM + WOFF;
        #pragma unroll
        for (int mt = 0; mt < 4; mt++) {
            int o  = ow * 64 + mt * 16 + g;
            float bl = __ldg(bsrc + o), bh = __ldg(bsrc + o + 8);
            #pragma unroll
            for (int nt = 0; nt < 4; nt++) {
                int px = ytile * 128 + pwv * 32 + nt * 8 + 2 * q;
                float2 v0 = make_float2(acc[mt][nt][0] + bl, acc[mt][nt][1] + bl);
                float2 v1 = make_float2(acc[mt][nt][2] + bh, acc[mt][nt][3] + bh);
                *reinterpret_cast<float2*>(
                    out + ((size_t)b * CDIM + o)     * NPX + px) = v0;
                *reinterpret_cast<float2*>(
                    out + ((size_t)b * CDIM + o + 8) * NPX + px) = v1;
            }
        }
    }
}

// Tail kernel: reset flags for the next graph replay (deterministic).
__global__ void zero_flags_kernel()
{
    int i = threadIdx.x;
    if (i < BB) g_flagW[i] = 0;
    for (int j = i; j < BB * 8; j += 256) g_flagP[j] = 0;
}

// ===========================================================================
extern "C" void kernel_launch(void* const* d_in, const int* in_sizes, int n_in,
                              void* d_out, int out_size)
{
    const float* qrep = (const float*)d_in[0];   // (64, 147584)
    const float* lhs  = (const float*)d_in[1];   // (64, 128, 32, 32)
    const float* rhs  = (const float*)d_in[2];   // (64, 128, 32, 32)
    const float* pw   = (const float*)d_in[3];   // (128, 256)
    const float* pb   = (const float*)d_in[4];   // (128,)
    float* out = (float*)d_out;                  // (64, 128, 32, 32)

    static bool init_done = false;
    if (!init_done) {
        cudaFuncSetAttribute(fused_kernel,
            cudaFuncAttributeMaxDynamicSharedMemorySize, FUSED_SMEM);
        init_done = true;
    }

    fused_kernel<<<1536, 256, FUSED_SMEM>>>(qrep, lhs, rhs, pw, pb, out);
    zero_flags_kernel<<<1, 256>>>();
}